// round 15
// baseline (speedup 1.0000x reference)
#include <cuda_runtime.h>
#include <cstdint>

// ---------------------------------------------------------------------------
// Quan_adder2d. k_prep (34 blocks): W quant/regrid/pack + wsum, x minmax +
// xpack. k_main: 296 persistent blocks, dynamic work-stealing over 448
// half-tiles (ho, n, fh, wo-half). Hot loop: min.u16x2 + dp2a
// (sum|.| = s*(WSUM + XSUM - 2*sum min)) on the global 16-bit x grid.
// ---------------------------------------------------------------------------

#define N_BATCH 4
#define C_IN    64
#define HW      28
#define F_OUT   64
#define KDIM    576
#define QX_MAX  65535.0f
#define QW_MAX  255.0f

#define MMB     32
#define PREPG   (2 + MMB)         // 34
#define NBLK    296               // 2 per SM, one wave
#define NTILES  448               // 28 ho x 4 n x 2 fh x 2 wh
#define THREADS 448
#define SLICES  8
#define CPP     4
#define TPS     56                // 8 fgrp x 7 wog

__device__ float    g_bmin[MMB];
__device__ float    g_bmax[MMB];
__device__ unsigned g_cnt  = 0;
__device__ unsigned g_tile = NBLK;
__device__ float    g_sprm[2];             // xscale, xzp
__device__ unsigned g_wsum[F_OUT];
__device__ unsigned g_swi[2 * 288 * 32];   // [fhalf][k'][f'] packed u16x2
__device__ unsigned g_qxi[N_BATCH * 32 * HW * HW];  // [n][cpair][h][w]

__device__ __forceinline__ unsigned minu2(unsigned a, unsigned b) {
    unsigned r;
    asm("min.u16x2 %0, %1, %2;" : "=r"(r) : "r"(a), "r"(b));
    return r;
}
#define DPB 0x00000101u   // dp2a byte pair (1,1): sums both u16 halves

// ---------------------------------------------------------------------------
#define PREP_SMEM (32 * 289 * 4)   // 36992 B

__global__ void __launch_bounds__(1024, 1) k_prep(const float* __restrict__ W,
                                                  const float* __restrict__ x) {
    extern __shared__ unsigned sp[];   // W blocks: [32 f][pitch 289] packed
    const int tid = threadIdx.x;

    // ---------------- minmax + xpack blocks (2..33) ----------------
    if (blockIdx.x >= 2) {
        const int bid = blockIdx.x - 2;
        const float4* x4 = (const float4*)x;
        float mn = 1e30f, mx = -1e30f;
        {
            const int base = bid * 1568;
            float4 v = x4[base + tid];
            mn = fminf(fminf(v.x, v.y), fminf(v.z, v.w));
            mx = fmaxf(fmaxf(v.x, v.y), fmaxf(v.z, v.w));
            if (tid < 544) {
                float4 u = x4[base + 1024 + tid];
                mn = fminf(mn, fminf(fminf(u.x, u.y), fminf(u.z, u.w)));
                mx = fmaxf(mx, fmaxf(fmaxf(u.x, u.y), fmaxf(u.z, u.w)));
            }
        }
        #pragma unroll
        for (int o = 16; o > 0; o >>= 1) {
            mn = fminf(mn, __shfl_xor_sync(0xffffffffu, mn, o));
            mx = fmaxf(mx, __shfl_xor_sync(0xffffffffu, mx, o));
        }
        __shared__ float smn[32], smx[32];
        int warp = tid >> 5, lane = tid & 31;
        if (lane == 0) { smn[warp] = mn; smx[warp] = mx; }
        __syncthreads();
        if (warp == 0) {
            mn = smn[lane];
            mx = smx[lane];
            #pragma unroll
            for (int o = 16; o > 0; o >>= 1) {
                mn = fminf(mn, __shfl_xor_sync(0xffffffffu, mn, o));
                mx = fmaxf(mx, __shfl_xor_sync(0xffffffffu, mx, o));
            }
            if (lane == 0) {
                g_bmin[bid] = mn;
                g_bmax[bid] = mx;
                __threadfence();
                atomicAdd(&g_cnt, 1u);
            }
        }
        __shared__ float prm[2];
        if (tid == 0) {
            while (atomicAdd(&g_cnt, 0u) < (unsigned)MMB) __nanosleep(64);
            float xmn = 1e30f, xmx = -1e30f;
            #pragma unroll 8
            for (int i = 0; i < MMB; ++i) {
                xmn = fminf(xmn, g_bmin[i]);
                xmx = fmaxf(xmx, g_bmax[i]);
            }
            float s = fmaxf(__fdiv_rn(xmx - xmn, QX_MAX), 1e-12f);
            prm[0] = s;
            prm[1] = rintf(__fdiv_rn(-xmn, s));
        }
        __syncthreads();
        const float s  = prm[0];
        const float zp = prm[1];
        const int pbase = bid * 3136;
        #pragma unroll
        for (int k = 0; k < 4; ++k) {
            int off = k * 1024 + tid;
            if (off < 3136) {
                int ib  = pbase + off;
                int hw  = ib % 784;
                int cpn = ib / 784;
                int cp  = cpn & 31;
                int n   = cpn >> 5;
                float a = x[(n * 64 + cp) * 784 + hw];
                float b = x[(n * 64 + cp + 32) * 784 + hw];
                unsigned vlo = (unsigned)fminf(
                    fmaxf(rintf(__fdiv_rn(a, s)) + zp, 0.0f), QX_MAX);
                unsigned vhi = (unsigned)fminf(
                    fmaxf(rintf(__fdiv_rn(b, s)) + zp, 0.0f), QX_MAX);
                g_qxi[ib] = vlo | (vhi << 16);
            }
        }
        return;
    }

    // ---------------- W blocks (0,1) ----------------
    const int b = blockIdx.x;
    if (b == 0 && tid == 0) g_tile = NBLK;   // reset steal counter (prev k_main done)
    const int warp = tid >> 5;
    const int lane = tid & 31;
    const int f    = b * 32 + warp;

    const float* wf = W + f * KDIM;
    float v[18];
    float mn = 1e30f, mx = -1e30f;
    #pragma unroll
    for (int t = 0; t < 18; ++t) {
        v[t] = wf[lane + t * 32];
        mn = fminf(mn, v[t]);
        mx = fmaxf(mx, v[t]);
    }
    #pragma unroll
    for (int o = 16; o > 0; o >>= 1) {
        mn = fminf(mn, __shfl_xor_sync(0xffffffffu, mn, o));
        mx = fmaxf(mx, __shfl_xor_sync(0xffffffffu, mx, o));
    }
    float scale = fmaxf(__fdiv_rn(mx - mn, QW_MAX), 1e-12f);
    float zp    = rintf(__fdiv_rn(-mn, scale));
    #pragma unroll
    for (int t = 0; t < 18; ++t) {
        float q = fminf(fmaxf(rintf(__fdiv_rn(v[t], scale)) + zp, 0.0f), QW_MAX);
        v[t] = (q - zp) * scale;
    }

    __shared__ float xs_s[2];
    if (tid == 0) {
        while (atomicAdd(&g_cnt, 0u) < (unsigned)MMB) __nanosleep(64);
        float xmn = 1e30f, xmx = -1e30f;
        #pragma unroll 8
        for (int i = 0; i < MMB; ++i) {
            xmn = fminf(xmn, g_bmin[i]);
            xmx = fmaxf(xmx, g_bmax[i]);
        }
        float xs = fmaxf(__fdiv_rn(xmx - xmn, QX_MAX), 1e-12f);
        xs_s[0] = xs;
        xs_s[1] = rintf(__fdiv_rn(-xmn, xs));
        if (b == 0) { g_sprm[0] = xs_s[0]; g_sprm[1] = xs_s[1]; }
    }
    __syncthreads();
    const float xs   = xs_s[0];
    const float xzp  = xs_s[1];
    const float invs = __fdiv_rn(1.0f, xs);

    unsigned wq[18];
    #pragma unroll
    for (int t = 0; t < 18; ++t)
        wq[t] = (unsigned)fminf(fmaxf(rintf(v[t] * invs) + xzp, 0.0f), 65535.0f);
    unsigned ssum = 0;
    #pragma unroll
    for (int t = 0; t < 9; ++t) {
        unsigned p = wq[t] | (wq[t + 9] << 16);
        sp[warp * 289 + lane + t * 32] = p;
        ssum = __dp2a_lo(p, DPB, ssum);
    }
    #pragma unroll
    for (int o = 16; o > 0; o >>= 1)
        ssum += __shfl_xor_sync(0xffffffffu, ssum, o);
    if (lane == 0) g_wsum[f] = ssum;
    __syncthreads();

    const int j  = tid & 31;
    const int kk = tid >> 5;
    #pragma unroll
    for (int p = 0; p < 9; ++p) {
        int k2 = p * 32 + kk;
        g_swi[b * 9216 + k2 * 32 + j] = sp[j * 289 + k2];
    }
}

// ---------------------------------------------------------------------------
// k_main: 296 persistent blocks, work-stealing over 448 half-tiles
// ---------------------------------------------------------------------------
#define SWI_OFF   0                 // [288][32]
#define SXI_OFF   9216              // [32 cp][3][16]
#define RED_OFF   10752             // 784 uint4 = 3136 u32
#define RPART_OFF 13888             // [16][8]
#define RS_OFF    14016             // [16]
#define SMEM_U32  14032
#define SMEM_BYTES (SMEM_U32 * 4)   // 56128

__global__ void __launch_bounds__(THREADS, 2) k_main(float* __restrict__ out) {
    const int tid = threadIdx.x;
    if (blockIdx.x == 0 && tid == 0) g_cnt = 0u;   // reset for next launch

    extern __shared__ unsigned smem[];
    unsigned* swi   = smem + SWI_OFF;
    unsigned* sxi   = smem + SXI_OFF;
    uint4*    red   = (uint4*)(smem + RED_OFF);
    unsigned* rpart = smem + RPART_OFF;
    unsigned* rs    = smem + RS_OFF;
    __shared__ int s_tile;

    const float    s   = g_sprm[0];
    const unsigned zpu = (unsigned)g_sprm[1];
    const unsigned zpp = zpu | (zpu << 16);

    const int slice = tid / TPS;
    const int t     = tid - slice * TPS;
    const int fgrp  = t & 7;
    const int wog   = t >> 3;             // 0..6
    const int f0    = fgrp * 4;
    const int wo0   = wog * 2;            // 2 wo per thread, half-tile = 14 wo
    const int cp0   = slice * CPP;

    int prev_fh = -1;
    bool first = true;

    for (;;) {
        if (tid == 0)
            s_tile = first ? (int)blockIdx.x : (int)atomicAdd(&g_tile, 1u);
        first = false;
        __syncthreads();                         // sync0 (also guards reuse)
        const int tile = s_tile;
        if (tile >= NTILES) break;

        const int fh = (tile < 224) ? 0 : 1;
        const int r  = tile - fh * 224;
        const int ho = r % 28;
        const int nz = r / 28;
        const int n  = nz & 3;
        const int wh = nz >> 2;                  // 0,1
        const int wbase = wh * 14;

        // stage W half only when fh changes
        if (fh != prev_fh) {
            const uint4* gsrc = (const uint4*)(g_swi + fh * 9216);
            uint4*       sdst = (uint4*)swi;
            for (int i = tid; i < 2304; i += THREADS) sdst[i] = gsrc[i];
            prev_fh = fh;
        }

        // stage packed x half-window [32cp][3][16]
        for (int idx = tid; idx < 1536; idx += THREADS) {
            int cp  = idx / 48;
            int rem = idx - cp * 48;
            int i   = rem >> 4;
            int cc  = rem & 15;
            int h   = ho + i - 1;
            int w   = wbase + cc - 1;
            unsigned v = zpp;
            if ((unsigned)h < (unsigned)HW && (unsigned)w < (unsigned)HW)
                v = g_qxi[((n * 32 + cp) * HW + h) * HW + w];
            sxi[idx] = v;
        }
        __syncthreads();                         // sync1

        // X_SUM column partials: col = tid>>3 (0..15), p = tid&7
        if (tid < 128) {
            int col = tid >> 3;
            int p   = tid & 7;
            unsigned xsum = 0;
            #pragma unroll
            for (int cc2 = 0; cc2 < 4; ++cc2)
                #pragma unroll
                for (int i = 0; i < 3; ++i)
                    xsum = __dp2a_lo(sxi[(p * 4 + cc2) * 48 + i * 16 + col],
                                     DPB, xsum);
            rpart[col * 8 + p] = xsum;
        }

        // ---- hot loop (4f x 2wo) ----
        unsigned acc[4][2];
        #pragma unroll
        for (int a = 0; a < 4; ++a) { acc[a][0] = 0u; acc[a][1] = 0u; }

        const unsigned* xrow = sxi + cp0 * 48 + wo0;
        const unsigned* wrow = swi + cp0 * 9 * 32 + f0;

        #pragma unroll
        for (int cp = 0; cp < CPP; ++cp) {
            #pragma unroll
            for (int i = 0; i < 3; ++i) {
                uint4 wp0 = *(const uint4*)(wrow + (i * 3 + 0) * 32);
                uint4 wp1 = *(const uint4*)(wrow + (i * 3 + 1) * 32);
                uint4 wp2 = *(const uint4*)(wrow + (i * 3 + 2) * 32);
                uint2 xa = *(const uint2*)(xrow + i * 16);
                uint2 xb = *(const uint2*)(xrow + i * 16 + 2);
                unsigned xsv[4] = { xa.x, xa.y, xb.x, xb.y };
                #pragma unroll
                for (int k = 0; k < 2; ++k) {
                    unsigned x0 = xsv[k], x1 = xsv[k + 1], x2 = xsv[k + 2];
                    acc[0][k] = __dp2a_lo(minu2(wp0.x, x0), DPB, acc[0][k]);
                    acc[1][k] = __dp2a_lo(minu2(wp0.y, x0), DPB, acc[1][k]);
                    acc[2][k] = __dp2a_lo(minu2(wp0.z, x0), DPB, acc[2][k]);
                    acc[3][k] = __dp2a_lo(minu2(wp0.w, x0), DPB, acc[3][k]);
                    acc[0][k] = __dp2a_lo(minu2(wp1.x, x1), DPB, acc[0][k]);
                    acc[1][k] = __dp2a_lo(minu2(wp1.y, x1), DPB, acc[1][k]);
                    acc[2][k] = __dp2a_lo(minu2(wp1.z, x1), DPB, acc[2][k]);
                    acc[3][k] = __dp2a_lo(minu2(wp1.w, x1), DPB, acc[3][k]);
                    acc[0][k] = __dp2a_lo(minu2(wp2.x, x2), DPB, acc[0][k]);
                    acc[1][k] = __dp2a_lo(minu2(wp2.y, x2), DPB, acc[1][k]);
                    acc[2][k] = __dp2a_lo(minu2(wp2.z, x2), DPB, acc[2][k]);
                    acc[3][k] = __dp2a_lo(minu2(wp2.w, x2), DPB, acc[3][k]);
                }
            }
            xrow += 48;
            wrow += 9 * 32;
        }

        // slices 1..7 publish partials
        if (slice > 0) {
            int base = ((slice - 1) * TPS + t) * 2;
            red[base]     = make_uint4(acc[0][0], acc[0][1], acc[1][0], acc[1][1]);
            red[base + 1] = make_uint4(acc[2][0], acc[2][1], acc[3][0], acc[3][1]);
        }
        __syncthreads();                         // sync2
        if (tid < 16) {
            unsigned xsum = 0;
            #pragma unroll
            for (int p = 0; p < 8; ++p) xsum += rpart[tid * 8 + p];
            rs[tid] = xsum;
        }
        if (slice == 0) {
            #pragma unroll
            for (int sl = 0; sl < 7; ++sl) {
                int base = (sl * TPS + t) * 2;
                uint4 A = red[base];
                uint4 B = red[base + 1];
                acc[0][0] += A.x; acc[0][1] += A.y;
                acc[1][0] += A.z; acc[1][1] += A.w;
                acc[2][0] += B.x; acc[2][1] += B.y;
                acc[3][0] += B.z; acc[3][1] += B.w;
            }
        }
        __syncthreads();                         // sync3
        if (slice == 0) {
            int xs0 = (int)(rs[wo0] + rs[wo0 + 1] + rs[wo0 + 2]);
            int xs1 = (int)(rs[wo0 + 1] + rs[wo0 + 2] + rs[wo0 + 3]);
            const int fbase = fh * 32 + f0;
            float* op = out + ((n * F_OUT + fbase) * HW + ho) * HW + wbase + wo0;
            #pragma unroll
            for (int fl = 0; fl < 4; ++fl) {
                int ws = (int)g_wsum[fbase + fl];
                float2 o;
                o.x = s * (float)(2 * (int)acc[fl][0] - ws - xs0);
                o.y = s * (float)(2 * (int)acc[fl][1] - ws - xs1);
                *(float2*)(op + fl * HW * HW) = o;
            }
        }
    }
}

extern "C" void kernel_launch(void* const* d_in, const int* in_sizes, int n_in,
                              void* d_out, int out_size) {
    const float* x = (const float*)d_in[0];
    const float* W = (const float*)d_in[1];
    float* out = (float*)d_out;

    cudaFuncSetAttribute(k_prep, cudaFuncAttributeMaxDynamicSharedMemorySize,
                         PREP_SMEM);
    cudaFuncSetAttribute(k_main, cudaFuncAttributeMaxDynamicSharedMemorySize,
                         SMEM_BYTES);

    k_prep<<<PREPG, 1024, PREP_SMEM>>>(W, x);
    k_main<<<NBLK, THREADS, SMEM_BYTES>>>(out);
}

// round 16
// speedup vs baseline: 1.1897x; 1.1897x over previous
#include <cuda_runtime.h>
#include <cstdint>

// ---------------------------------------------------------------------------
// Quan_adder2d. PDL-overlapped two kernels:
//  k_prep (34 blocks): triggers programmatic launch at entry.
//    blocks 0,1 -> W quant/regrid/pack + wsum (spin on minmax)
//    blocks 2..33 -> x minmax partials
//  k_main (28,4,2): PSS secondary. Stages raw x BEFORE gridsync (overlaps
//    prep), then quantizes in smem, stages W, runs the min+dp2a hot loop.
//  sum|.| = s * (W_SUM[f] + X_SUM[win] - 2*sum min(w_int, x_int))
// ---------------------------------------------------------------------------

#define N_BATCH 4
#define C_IN    64
#define HW      28
#define F_OUT   64
#define KDIM    576
#define QX_MAX  65535.0f
#define QW_MAX  255.0f

#define MMB     32
#define PREPG   (2 + MMB)         // 34
#define SLICES  8
#define CPP     4
#define TPS     56                // 8 fgrp x 7 wog
#define THREADS (SLICES*TPS)      // 448

__device__ float    g_bmin[MMB];
__device__ float    g_bmax[MMB];
__device__ unsigned g_cnt = 0;
__device__ float    g_sprm[2];             // xscale, xzp
__device__ unsigned g_wsum[F_OUT];
__device__ unsigned g_swi[2 * 288 * 32];   // [fhalf][k'][f'] packed u16x2

__device__ __forceinline__ unsigned minu2(unsigned a, unsigned b) {
    unsigned r;
    asm("min.u16x2 %0, %1, %2;" : "=r"(r) : "r"(a), "r"(b));
    return r;
}
#define DPB 0x00000101u   // dp2a byte pair (1,1): sums both u16 halves

// ---------------------------------------------------------------------------
#define PREP_SMEM (32 * 289 * 4)   // 36992 B (W path staging, pitch 289)

__global__ void __launch_bounds__(1024, 1) k_prep(const float* __restrict__ W,
                                                  const float* __restrict__ x) {
    // Let the PDL secondary (k_main) launch immediately.
    cudaTriggerProgrammaticLaunchCompletion();

    extern __shared__ unsigned sp[];   // W blocks: [32 f][pitch 289] packed
    const int tid = threadIdx.x;

    // ---------------- x min/max partial blocks (2..33) ----------------
    if (blockIdx.x >= 2) {
        const float4* x4 = (const float4*)x;
        const int n4 = (N_BATCH * C_IN * HW * HW) / 4;
        int bid = blockIdx.x - 2;
        float mn = 1e30f, mx = -1e30f;
        for (int i = bid * 1024 + tid; i < n4; i += MMB * 1024) {
            float4 v = x4[i];
            mn = fminf(fminf(fminf(mn, v.x), v.y), fminf(v.z, v.w));
            mx = fmaxf(fmaxf(fmaxf(mx, v.x), v.y), fmaxf(v.z, v.w));
        }
        #pragma unroll
        for (int o = 16; o > 0; o >>= 1) {
            mn = fminf(mn, __shfl_xor_sync(0xffffffffu, mn, o));
            mx = fmaxf(mx, __shfl_xor_sync(0xffffffffu, mx, o));
        }
        __shared__ float smn[32], smx[32];
        int warp = tid >> 5, lane = tid & 31;
        if (lane == 0) { smn[warp] = mn; smx[warp] = mx; }
        __syncthreads();
        if (warp == 0) {
            mn = smn[lane];
            mx = smx[lane];
            #pragma unroll
            for (int o = 16; o > 0; o >>= 1) {
                mn = fminf(mn, __shfl_xor_sync(0xffffffffu, mn, o));
                mx = fmaxf(mx, __shfl_xor_sync(0xffffffffu, mx, o));
            }
            if (lane == 0) {
                g_bmin[bid] = mn;
                g_bmax[bid] = mx;
                __threadfence();
                atomicAdd(&g_cnt, 1u);
            }
        }
        return;
    }

    // ---------------- W blocks (0,1): quant + regrid + pack + wsum ----------
    const int b    = blockIdx.x;
    const int warp = tid >> 5;
    const int lane = tid & 31;
    const int f    = b * 32 + warp;

    const float* wf = W + f * KDIM;
    float v[18];
    float mn = 1e30f, mx = -1e30f;
    #pragma unroll
    for (int t = 0; t < 18; ++t) {       // k = lane + t*32
        v[t] = wf[lane + t * 32];
        mn = fminf(mn, v[t]);
        mx = fmaxf(mx, v[t]);
    }
    #pragma unroll
    for (int o = 16; o > 0; o >>= 1) {
        mn = fminf(mn, __shfl_xor_sync(0xffffffffu, mn, o));
        mx = fmaxf(mx, __shfl_xor_sync(0xffffffffu, mx, o));
    }
    float scale = fmaxf(__fdiv_rn(mx - mn, QW_MAX), 1e-12f);
    float zp    = rintf(__fdiv_rn(-mn, scale));
    const float invw = __fdiv_rn(1.0f, scale);
    #pragma unroll
    for (int t = 0; t < 18; ++t) {       // dequantized weight (float)
        float q = fminf(fmaxf(rintf(v[t] * invw) + zp, 0.0f), QW_MAX);
        v[t] = (q - zp) * scale;
    }

    __shared__ float xs_s[2];
    if (tid == 0) {
        while (atomicAdd(&g_cnt, 0u) < (unsigned)MMB) __nanosleep(64);
        float xmn = 1e30f, xmx = -1e30f;
        #pragma unroll 8
        for (int i = 0; i < MMB; ++i) {
            xmn = fminf(xmn, g_bmin[i]);
            xmx = fmaxf(xmx, g_bmax[i]);
        }
        float xs = fmaxf(__fdiv_rn(xmx - xmn, QX_MAX), 1e-12f);
        xs_s[0] = xs;
        xs_s[1] = rintf(__fdiv_rn(-xmn, xs));
        if (b == 0) { g_sprm[0] = xs_s[0]; g_sprm[1] = xs_s[1]; }
    }
    __syncthreads();
    const float xs   = xs_s[0];
    const float xzp  = xs_s[1];
    const float invs = __fdiv_rn(1.0f, xs);

    unsigned wq[18];
    #pragma unroll
    for (int t = 0; t < 18; ++t)
        wq[t] = (unsigned)fminf(fmaxf(rintf(v[t] * invs) + xzp, 0.0f), 65535.0f);
    unsigned ssum = 0;
    #pragma unroll
    for (int t = 0; t < 9; ++t) {        // pair: k'=lane+t*32 with k'+288
        unsigned p = wq[t] | (wq[t + 9] << 16);
        sp[warp * 289 + lane + t * 32] = p;
        ssum = __dp2a_lo(p, DPB, ssum);
    }
    #pragma unroll
    for (int o = 16; o > 0; o >>= 1)
        ssum += __shfl_xor_sync(0xffffffffu, ssum, o);
    if (lane == 0) g_wsum[f] = ssum;
    __syncthreads();

    const int j  = tid & 31;
    const int kk = tid >> 5;
    #pragma unroll
    for (int p = 0; p < 9; ++p) {
        int k2 = p * 32 + kk;
        g_swi[b * 9216 + k2 * 32 + j] = sp[j * 289 + k2];
    }
}

// ---------------------------------------------------------------------------
// k_main: grid (28 ho, 4 n, 2 fhalf), 448 threads, 2 blocks/SM, PDL secondary
// smem: SWI | SXI | union(SXR raw x, RED+RPART+RS)
// ---------------------------------------------------------------------------
#define SWI_OFF   0                    // 9216
#define SXI_OFF   9216                 // 3072
#define UN_OFF    12288
#define SXR_OFF   12288                // 5760 floats (raw x window)
#define RED_OFF   12288                // 6272 (after hot loop; SXR dead)
#define RPART_OFF 18560                // 240
#define RS_OFF    18800                // 30
#define SMEM_U32  18832
#define SMEM_BYTES (SMEM_U32 * 4)      // 75328

__global__ void __launch_bounds__(THREADS, 2) k_main(const float* __restrict__ x,
                                                     float* __restrict__ out) {
    const int ho  = blockIdx.x;
    const int n   = blockIdx.y;
    const int fh  = blockIdx.z;
    const int tid = threadIdx.x;

    extern __shared__ unsigned smem[];
    unsigned* swi   = smem + SWI_OFF;
    unsigned* sxi   = smem + SXI_OFF;
    float*    sxr   = (float*)(smem + SXR_OFF);
    uint4*    red   = (uint4*)(smem + RED_OFF);
    unsigned* rpart = smem + RPART_OFF;
    unsigned* rs    = smem + RS_OFF;

    // ---- phase 1 (prep-independent, overlaps k_prep): raw x staging ----
    for (int idx = tid; idx < 5760; idx += THREADS) {
        int c   = idx / 90;
        int rem = idx - c * 90;
        int i   = rem / 30;
        int col = rem - i * 30;
        int h   = ho + i - 1;
        int w   = col - 1;
        float v = 0.0f;
        if ((unsigned)h < (unsigned)HW && (unsigned)w < (unsigned)HW)
            v = x[((n * C_IN + c) * HW + h) * HW + w];
        sxr[idx] = v;
    }

    // ---- wait for k_prep outputs ----
    cudaGridDependencySynchronize();
    if (tid == 0 && ho == 0 && n == 0 && fh == 0) g_cnt = 0u;

    const float s    = g_sprm[0];
    const float zp   = g_sprm[1];
    const float invs = __fdiv_rn(1.0f, s);

    // stage packed W half (L2 resident)
    {
        const uint4* gsrc = (const uint4*)(g_swi + fh * 9216);
        uint4*       sdst = (uint4*)swi;
        for (int i = tid; i < 2304; i += THREADS) sdst[i] = gsrc[i];
    }
    __syncthreads();   // sxr fully written before quant reads (also W visible)

    // quantize + pack x from smem (quant(0) == zp handles padding exactly)
    for (int idx = tid; idx < 2880; idx += THREADS) {
        int c   = idx / 90;
        int rem = idx - c * 90;
        int i   = rem / 30;
        int col = rem - i * 30;
        float a  = sxr[c * 90 + i * 30 + col];
        float bb = sxr[(c + 32) * 90 + i * 30 + col];
        unsigned vlo = (unsigned)fminf(fmaxf(rintf(a * invs) + zp, 0.0f), QX_MAX);
        unsigned vhi = (unsigned)fminf(fmaxf(rintf(bb * invs) + zp, 0.0f), QX_MAX);
        sxi[c * 96 + i * 32 + col] = vlo | (vhi << 16);
    }
    __syncthreads();   // sxr dead after this

    // X window column-sum partials (X_SUM correction)
    if (tid < 240) {
        int col = tid >> 3;
        int p   = tid & 7;
        unsigned ssum = 0;
        #pragma unroll
        for (int cc = 0; cc < 4; ++cc)
            #pragma unroll
            for (int i = 0; i < 3; ++i)
                ssum = __dp2a_lo(sxi[(p * 4 + cc) * 96 + i * 32 + col], DPB, ssum);
        rpart[col * 8 + p] = ssum;
    }

    // ---- hot loop ----
    const int slice = tid / TPS;
    const int t     = tid - slice * TPS;
    const int fgrp  = t & 7;
    const int wog   = t >> 3;
    const int f0    = fgrp * 4;
    const int wo0   = wog * 4;
    const int cp0   = slice * CPP;

    unsigned acc[4][4];
    #pragma unroll
    for (int a = 0; a < 4; ++a)
        #pragma unroll
        for (int b2 = 0; b2 < 4; ++b2) acc[a][b2] = 0u;

    const unsigned* xrow = sxi + cp0 * 96;
    const unsigned* wrow = swi + cp0 * 9 * 32 + f0;

    #pragma unroll
    for (int cp = 0; cp < CPP; ++cp) {
        #pragma unroll
        for (int i = 0; i < 3; ++i) {
            uint4 wp0 = *(const uint4*)(wrow + (i * 3 + 0) * 32);
            uint4 wp1 = *(const uint4*)(wrow + (i * 3 + 1) * 32);
            uint4 wp2 = *(const uint4*)(wrow + (i * 3 + 2) * 32);
            const unsigned* xr = xrow + i * 32 + wo0;
            uint4 xa = *(const uint4*)xr;
            uint2 xb = *(const uint2*)(xr + 4);
            unsigned xsv[6] = { xa.x, xa.y, xa.z, xa.w, xb.x, xb.y };
            #pragma unroll
            for (int k = 0; k < 4; ++k) {
                unsigned x0 = xsv[k], x1 = xsv[k + 1], x2 = xsv[k + 2];
                acc[0][k] = __dp2a_lo(minu2(wp0.x, x0), DPB, acc[0][k]);
                acc[1][k] = __dp2a_lo(minu2(wp0.y, x0), DPB, acc[1][k]);
                acc[2][k] = __dp2a_lo(minu2(wp0.z, x0), DPB, acc[2][k]);
                acc[3][k] = __dp2a_lo(minu2(wp0.w, x0), DPB, acc[3][k]);
                acc[0][k] = __dp2a_lo(minu2(wp1.x, x1), DPB, acc[0][k]);
                acc[1][k] = __dp2a_lo(minu2(wp1.y, x1), DPB, acc[1][k]);
                acc[2][k] = __dp2a_lo(minu2(wp1.z, x1), DPB, acc[2][k]);
                acc[3][k] = __dp2a_lo(minu2(wp1.w, x1), DPB, acc[3][k]);
                acc[0][k] = __dp2a_lo(minu2(wp2.x, x2), DPB, acc[0][k]);
                acc[1][k] = __dp2a_lo(minu2(wp2.y, x2), DPB, acc[1][k]);
                acc[2][k] = __dp2a_lo(minu2(wp2.z, x2), DPB, acc[2][k]);
                acc[3][k] = __dp2a_lo(minu2(wp2.w, x2), DPB, acc[3][k]);
            }
        }
        xrow += 96;
        wrow += 9 * 32;
    }

    uint4 va[4];
    #pragma unroll
    for (int fl = 0; fl < 4; ++fl)
        va[fl] = make_uint4(acc[fl][0], acc[fl][1], acc[fl][2], acc[fl][3]);

    // flat reduction: slices 1..7 store; slice 0 sums all (SXR dead -> RED ok)
    if (slice > 0) {
        #pragma unroll
        for (int fl = 0; fl < 4; ++fl)
            red[(((slice - 1) * TPS + t) << 2) + fl] = va[fl];
    }
    __syncthreads();
    if (tid < 30) {
        unsigned ssum = 0;
        #pragma unroll
        for (int p = 0; p < 8; ++p) ssum += rpart[tid * 8 + p];
        rs[tid] = ssum;
    }
    if (slice == 0) {
        #pragma unroll
        for (int sl = 0; sl < 7; ++sl) {
            #pragma unroll
            for (int fl = 0; fl < 4; ++fl) {
                uint4 o = red[((sl * TPS + t) << 2) + fl];
                va[fl].x += o.x; va[fl].y += o.y;
                va[fl].z += o.z; va[fl].w += o.w;
            }
        }
    }
    __syncthreads();
    if (slice == 0) {
        int xsum[4];
        #pragma unroll
        for (int k = 0; k < 4; ++k)
            xsum[k] = (int)(rs[wo0 + k] + rs[wo0 + k + 1] + rs[wo0 + k + 2]);
        const int fbase = fh * 32 + f0;
        float* op = out + ((n * F_OUT + fbase) * HW + ho) * HW + wo0;
        #pragma unroll
        for (int fl = 0; fl < 4; ++fl) {
            int ws = (int)g_wsum[fbase + fl];
            float4 o;
            o.x = s * (float)(2 * (int)va[fl].x - ws - xsum[0]);
            o.y = s * (float)(2 * (int)va[fl].y - ws - xsum[1]);
            o.z = s * (float)(2 * (int)va[fl].z - ws - xsum[2]);
            o.w = s * (float)(2 * (int)va[fl].w - ws - xsum[3]);
            *(float4*)(op + fl * HW * HW) = o;
        }
    }
}

extern "C" void kernel_launch(void* const* d_in, const int* in_sizes, int n_in,
                              void* d_out, int out_size) {
    const float* x = (const float*)d_in[0];
    const float* W = (const float*)d_in[1];
    float* out = (float*)d_out;

    cudaFuncSetAttribute(k_prep, cudaFuncAttributeMaxDynamicSharedMemorySize,
                         PREP_SMEM);
    cudaFuncSetAttribute(k_main, cudaFuncAttributeMaxDynamicSharedMemorySize,
                         SMEM_BYTES);

    k_prep<<<PREPG, 1024, PREP_SMEM>>>(W, x);

    // k_main as PDL secondary: k_prep triggers launch at entry, so k_main's
    // raw-x staging overlaps k_prep execution.
    cudaLaunchConfig_t cfg = {};
    cfg.gridDim  = dim3(HW, N_BATCH, 2);
    cfg.blockDim = dim3(THREADS, 1, 1);
    cfg.dynamicSmemBytes = SMEM_BYTES;
    cudaLaunchAttribute attrs[1];
    attrs[0].id = cudaLaunchAttributeProgrammaticStreamSerialization;
    attrs[0].val.programmaticStreamSerializationAllowed = 1;
    cfg.attrs = attrs;
    cfg.numAttrs = 1;
    cudaLaunchKernelEx(&cfg, k_main, x, out);
}